// round 1
// baseline (speedup 1.0000x reference)
#include <cuda_runtime.h>

#define DMODEL 512
#define NHEAD  8
#define DK     64
#define BATCH  2
#define SEQ    4096
#define MTOT   (BATCH*SEQ)   // 8192

// Scratch (static device arrays — allowed; no runtime allocation)
__device__ float g_qh[(size_t)BATCH*NHEAD*SEQ*DK];   // [B,H,S,Dk], pre-scaled by 1/8
__device__ float g_kh[(size_t)BATCH*NHEAD*SEQ*DK];
__device__ float g_vh[(size_t)BATCH*NHEAD*SEQ*DK];
__device__ float g_att[(size_t)BATCH*SEQ*DMODEL];    // attention out, [B,S,D]

// ---------------------------------------------------------------------------
// GEMM: Y = (X @ W^T + bias) * scale
// X: [M=8192, K=512] row-major, W: [N=512, K=512] row-major (torch Linear)
// HEAD_LAYOUT=true  -> scatter to [B,H,S,Dk]
// HEAD_LAYOUT=false -> plain [M, N]
// Tiles: 128x128x8, 256 threads, 8x8 per thread.
// ---------------------------------------------------------------------------
template<bool HEAD_LAYOUT>
__global__ __launch_bounds__(256, 2)
void gemm_bias_kernel(const float* __restrict__ X, const float* __restrict__ W,
                      const float* __restrict__ bias, float* __restrict__ Y,
                      float scale)
{
    __shared__ float As[8][132];
    __shared__ float Bs[8][132];

    const int m0  = blockIdx.y * 128;
    const int n0  = blockIdx.x * 128;
    const int tid = threadIdx.x;
    const int tx  = tid & 15;
    const int ty  = tid >> 4;
    const int lrow = tid >> 1;          // 0..127
    const int lk4  = (tid & 1) * 4;     // 0 or 4

    float acc[8][8];
#pragma unroll
    for (int i = 0; i < 8; i++)
#pragma unroll
        for (int j = 0; j < 8; j++) acc[i][j] = 0.f;

    const float* Xp = X + (size_t)(m0 + lrow) * DMODEL + lk4;
    const float* Wp = W + (size_t)(n0 + lrow) * DMODEL + lk4;

    for (int k0 = 0; k0 < DMODEL; k0 += 8) {
        float4 a = *(const float4*)(Xp + k0);
        float4 b = *(const float4*)(Wp + k0);
        __syncthreads();
        As[lk4 + 0][lrow] = a.x; As[lk4 + 1][lrow] = a.y;
        As[lk4 + 2][lrow] = a.z; As[lk4 + 3][lrow] = a.w;
        Bs[lk4 + 0][lrow] = b.x; Bs[lk4 + 1][lrow] = b.y;
        Bs[lk4 + 2][lrow] = b.z; Bs[lk4 + 3][lrow] = b.w;
        __syncthreads();

#pragma unroll
        for (int kk = 0; kk < 8; kk++) {
            float av[8], bv[8];
            *(float4*)&av[0] = *(const float4*)&As[kk][ty * 8];
            *(float4*)&av[4] = *(const float4*)&As[kk][ty * 8 + 4];
            *(float4*)&bv[0] = *(const float4*)&Bs[kk][tx * 8];
            *(float4*)&bv[4] = *(const float4*)&Bs[kk][tx * 8 + 4];
#pragma unroll
            for (int i = 0; i < 8; i++)
#pragma unroll
                for (int j = 0; j < 8; j++)
                    acc[i][j] = fmaf(av[i], bv[j], acc[i][j]);
        }
    }

#pragma unroll
    for (int i = 0; i < 8; i++) {
        const int m  = m0 + ty * 8 + i;
        const int bb = m >> 12;          // / 4096
        const int ss = m & 4095;
#pragma unroll
        for (int j = 0; j < 8; j++) {
            const int n = n0 + tx * 8 + j;
            const float val = (acc[i][j] + bias[n]) * scale;
            if (HEAD_LAYOUT) {
                const int h = n >> 6, d = n & 63;
                Y[(((size_t)(bb * NHEAD + h)) * SEQ + ss) * DK + d] = val;
            } else {
                Y[(size_t)m * DMODEL + n] = val;
            }
        }
    }
}

// ---------------------------------------------------------------------------
// Flash attention: per (b,h), 64-query tiles over 64-key tiles, Dk=64.
// 256 threads = 16x16 grid, 4x4 micro-tiles for QK^T and PV.
// Q pre-scaled by 1/sqrt(Dk) at projection time.
// Output written in [B,S,D] layout (heads concatenated).
// ---------------------------------------------------------------------------
#define QP 68   // padded pitch (floats), 16B-aligned rows
#define ATT_SMEM_FLOATS (3*64*QP + 64*64)

__global__ __launch_bounds__(256)
void attn_kernel()
{
    extern __shared__ float sm[];
    float* Qs = sm;                  // [d][r] pitch QP
    float* Ks = sm + 64 * QP;        // [d][t] pitch QP
    float* Ps = sm + 2 * 64 * QP;    // [t][r] pitch QP
    float* Vs = sm + 3 * 64 * QP;    // [t][d] pitch 64

    const int bh = blockIdx.y;
    const int q0 = blockIdx.x * 64;
    const int tid = threadIdx.x;
    const int tx  = tid & 15;
    const int ty  = tid >> 4;
    const int lt  = tid >> 2;          // 0..63
    const int ld  = (tid & 3) * 16;    // 0,16,32,48

    const float* Qg = g_qh + (size_t)bh * SEQ * DK;
    const float* Kg = g_kh + (size_t)bh * SEQ * DK;
    const float* Vg = g_vh + (size_t)bh * SEQ * DK;

    // Load Q tile once (transposed: Qs[d][r])
#pragma unroll
    for (int i = 0; i < 4; i++) {
        const int d = ld + i * 4;
        float4 qv = *(const float4*)&Qg[(size_t)(q0 + lt) * DK + d];
        Qs[(d + 0) * QP + lt] = qv.x; Qs[(d + 1) * QP + lt] = qv.y;
        Qs[(d + 2) * QP + lt] = qv.z; Qs[(d + 3) * QP + lt] = qv.w;
    }

    float o[4][4];
    float mi[4], li[4];
#pragma unroll
    for (int i = 0; i < 4; i++) {
        mi[i] = -1e30f; li[i] = 0.f;
#pragma unroll
        for (int j = 0; j < 4; j++) o[i][j] = 0.f;
    }

    for (int kt = 0; kt < SEQ / 64; kt++) {
        const float* Kt = Kg + (size_t)kt * 64 * DK;
        const float* Vt = Vg + (size_t)kt * 64 * DK;

        __syncthreads();   // prev PV done (and Q visible on first iter)
#pragma unroll
        for (int i = 0; i < 4; i++) {
            const int d = ld + i * 4;
            float4 kv = *(const float4*)&Kt[(size_t)lt * DK + d];
            Ks[(d + 0) * QP + lt] = kv.x; Ks[(d + 1) * QP + lt] = kv.y;
            Ks[(d + 2) * QP + lt] = kv.z; Ks[(d + 3) * QP + lt] = kv.w;
            float4 vv = *(const float4*)&Vt[(size_t)lt * DK + d];
            *(float4*)&Vs[lt * 64 + d] = vv;
        }
        __syncthreads();

        // S = Q @ K^T (Q pre-scaled)
        float sc[4][4];
#pragma unroll
        for (int i = 0; i < 4; i++)
#pragma unroll
            for (int j = 0; j < 4; j++) sc[i][j] = 0.f;

#pragma unroll 8
        for (int d = 0; d < 64; d++) {
            float qa[4], ka[4];
            *(float4*)qa = *(const float4*)&Qs[d * QP + ty * 4];
            *(float4*)ka = *(const float4*)&Ks[d * QP + tx * 4];
#pragma unroll
            for (int i = 0; i < 4; i++)
#pragma unroll
                for (int j = 0; j < 4; j++)
                    sc[i][j] = fmaf(qa[i], ka[j], sc[i][j]);
        }

        // online softmax (row reductions across the 16 tx lanes)
        float corr[4], rsum[4];
#pragma unroll
        for (int i = 0; i < 4; i++) {
            float t = fmaxf(fmaxf(sc[i][0], sc[i][1]), fmaxf(sc[i][2], sc[i][3]));
#pragma unroll
            for (int w = 1; w < 16; w <<= 1)
                t = fmaxf(t, __shfl_xor_sync(0xffffffffu, t, w));
            const float mn = fmaxf(mi[i], t);
            corr[i] = __expf(mi[i] - mn);
            mi[i] = mn;
            rsum[i] = 0.f;
        }
#pragma unroll
        for (int i = 0; i < 4; i++)
#pragma unroll
            for (int j = 0; j < 4; j++) {
                const float p = __expf(sc[i][j] - mi[i]);
                rsum[i] += p;
                Ps[(tx * 4 + j) * QP + ty * 4 + i] = p;   // transposed
            }
#pragma unroll
        for (int i = 0; i < 4; i++) {
            float t = rsum[i];
#pragma unroll
            for (int w = 1; w < 16; w <<= 1)
                t += __shfl_xor_sync(0xffffffffu, t, w);
            li[i] = li[i] * corr[i] + t;
#pragma unroll
            for (int j = 0; j < 4; j++) o[i][j] *= corr[i];
        }
        __syncthreads();   // Ps complete before PV

        // O += P @ V
#pragma unroll 8
        for (int t = 0; t < 64; t++) {
            float pa[4], va[4];
            *(float4*)pa = *(const float4*)&Ps[t * QP + ty * 4];
            *(float4*)va = *(const float4*)&Vs[t * 64 + tx * 4];
#pragma unroll
            for (int i = 0; i < 4; i++)
#pragma unroll
                for (int j = 0; j < 4; j++)
                    o[i][j] = fmaf(pa[i], va[j], o[i][j]);
        }
    }

    // epilogue: normalize, write [B,S,D] with heads concatenated
    const int bb = bh >> 3, hh = bh & 7;
#pragma unroll
    for (int i = 0; i < 4; i++) {
        const float inv = 1.0f / li[i];
        const int ss = q0 + ty * 4 + i;
        float4 r;
        r.x = o[i][0] * inv; r.y = o[i][1] * inv;
        r.z = o[i][2] * inv; r.w = o[i][3] * inv;
        *(float4*)&g_att[((size_t)(bb * SEQ + ss)) * DMODEL + hh * DK + tx * 4] = r;
    }
}

// ---------------------------------------------------------------------------
extern "C" void kernel_launch(void* const* d_in, const int* in_sizes, int n_in,
                              void* d_out, int out_size)
{
    const float* q  = (const float*)d_in[0];
    const float* k  = (const float*)d_in[1];
    const float* v  = (const float*)d_in[2];
    const float* wq = (const float*)d_in[3];
    const float* bq = (const float*)d_in[4];
    const float* wk = (const float*)d_in[5];
    const float* bk = (const float*)d_in[6];
    const float* wv = (const float*)d_in[7];
    const float* bv = (const float*)d_in[8];
    const float* wo = (const float*)d_in[9];
    const float* bo = (const float*)d_in[10];

    float *qh, *kh, *vh, *att;
    cudaGetSymbolAddress((void**)&qh,  g_qh);
    cudaGetSymbolAddress((void**)&kh,  g_kh);
    cudaGetSymbolAddress((void**)&vh,  g_vh);
    cudaGetSymbolAddress((void**)&att, g_att);

    const int att_smem = ATT_SMEM_FLOATS * (int)sizeof(float);  // 68608 B
    cudaFuncSetAttribute(attn_kernel,
                         cudaFuncAttributeMaxDynamicSharedMemorySize, att_smem);

    dim3 blk(256);
    dim3 gg(DMODEL / 128, MTOT / 128);   // (4, 64)

    // scale 1/sqrt(Dk) = 0.125 fused into Q projection
    gemm_bias_kernel<true><<<gg, blk>>>(q, wq, bq, qh, 0.125f);
    gemm_bias_kernel<true><<<gg, blk>>>(k, wk, bk, kh, 1.0f);
    gemm_bias_kernel<true><<<gg, blk>>>(v, wv, bv, vh, 1.0f);

    attn_kernel<<<dim3(SEQ / 64, BATCH * NHEAD), blk, att_smem>>>();

    gemm_bias_kernel<false><<<gg, blk>>>(att, wo, bo, (float*)d_out, 1.0f);
}

// round 2
// speedup vs baseline: 2.3634x; 2.3634x over previous
#include <cuda_runtime.h>
#include <cstdint>

#define DMODEL 512
#define NHEAD  8
#define DK     64
#define BATCH  2
#define SEQ    4096
#define MTOT   (BATCH*SEQ)   // 8192

// Scratch (static device arrays — no runtime allocation)
__device__ float g_qh[(size_t)BATCH*NHEAD*SEQ*DK];   // [B,H,S,Dk], pre-scaled by 1/8
__device__ float g_kh[(size_t)BATCH*NHEAD*SEQ*DK];
__device__ float g_vh[(size_t)BATCH*NHEAD*SEQ*DK];
__device__ float g_att[(size_t)BATCH*SEQ*DMODEL];    // attention out, [B,S,D]

// ---------------------------------------------------------------------------
// fp32 GEMM: Y = (X @ W^T + bias) * scale   (unchanged from R1)
// ---------------------------------------------------------------------------
template<bool HEAD_LAYOUT>
__global__ __launch_bounds__(256, 2)
void gemm_bias_kernel(const float* __restrict__ X, const float* __restrict__ W,
                      const float* __restrict__ bias, float* __restrict__ Y,
                      float scale)
{
    __shared__ float As[8][132];
    __shared__ float Bs[8][132];

    const int m0  = blockIdx.y * 128;
    const int n0  = blockIdx.x * 128;
    const int tid = threadIdx.x;
    const int tx  = tid & 15;
    const int ty  = tid >> 4;
    const int lrow = tid >> 1;
    const int lk4  = (tid & 1) * 4;

    float acc[8][8];
#pragma unroll
    for (int i = 0; i < 8; i++)
#pragma unroll
        for (int j = 0; j < 8; j++) acc[i][j] = 0.f;

    const float* Xp = X + (size_t)(m0 + lrow) * DMODEL + lk4;
    const float* Wp = W + (size_t)(n0 + lrow) * DMODEL + lk4;

    for (int k0 = 0; k0 < DMODEL; k0 += 8) {
        float4 a = *(const float4*)(Xp + k0);
        float4 b = *(const float4*)(Wp + k0);
        __syncthreads();
        As[lk4 + 0][lrow] = a.x; As[lk4 + 1][lrow] = a.y;
        As[lk4 + 2][lrow] = a.z; As[lk4 + 3][lrow] = a.w;
        Bs[lk4 + 0][lrow] = b.x; Bs[lk4 + 1][lrow] = b.y;
        Bs[lk4 + 2][lrow] = b.z; Bs[lk4 + 3][lrow] = b.w;
        __syncthreads();

#pragma unroll
        for (int kk = 0; kk < 8; kk++) {
            float av[8], bv[8];
            *(float4*)&av[0] = *(const float4*)&As[kk][ty * 8];
            *(float4*)&av[4] = *(const float4*)&As[kk][ty * 8 + 4];
            *(float4*)&bv[0] = *(const float4*)&Bs[kk][tx * 8];
            *(float4*)&bv[4] = *(const float4*)&Bs[kk][tx * 8 + 4];
#pragma unroll
            for (int i = 0; i < 8; i++)
#pragma unroll
                for (int j = 0; j < 8; j++)
                    acc[i][j] = fmaf(av[i], bv[j], acc[i][j]);
        }
    }

#pragma unroll
    for (int i = 0; i < 8; i++) {
        const int m  = m0 + ty * 8 + i;
        const int bb = m >> 12;
        const int ss = m & 4095;
#pragma unroll
        for (int j = 0; j < 8; j++) {
            const int n = n0 + tx * 8 + j;
            const float val = (acc[i][j] + bias[n]) * scale;
            if (HEAD_LAYOUT) {
                const int h = n >> 6, d = n & 63;
                Y[(((size_t)(bb * NHEAD + h)) * SEQ + ss) * DK + d] = val;
            } else {
                Y[(size_t)m * DMODEL + n] = val;
            }
        }
    }
}

// ---------------------------------------------------------------------------
// tf32 tensor-core flash attention.
// Block: 128 threads = 4 warps, 64 query rows (16/warp), key tiles of 64.
// mma.sync.m16n8k8 tf32 with fp32 accumulate for both QK^T and PV.
// Q pre-scaled by 1/8 at projection. P routed through smem (Q buffer reuse,
// intra-warp only -> __syncwarp). Pitch 68 => conflict-free fragment LDS.
// ---------------------------------------------------------------------------
#define AP 68
#define ATT_SMEM_BYTES (3 * 64 * AP * 4)   // 52224

__device__ __forceinline__ uint32_t f2tf(float f) {
    uint32_t u;
    asm("cvt.rna.tf32.f32 %0, %1;" : "=r"(u) : "f"(f));
    return u;
}

__device__ __forceinline__ void mma_tf32(float* d, const uint32_t* a,
                                         uint32_t b0, uint32_t b1) {
    asm volatile(
        "mma.sync.aligned.m16n8k8.row.col.f32.tf32.tf32.f32 "
        "{%0,%1,%2,%3}, {%4,%5,%6,%7}, {%8,%9}, {%0,%1,%2,%3};\n"
        : "+f"(d[0]), "+f"(d[1]), "+f"(d[2]), "+f"(d[3])
        : "r"(a[0]), "r"(a[1]), "r"(a[2]), "r"(a[3]), "r"(b0), "r"(b1));
}

__global__ __launch_bounds__(128)
void attn_mma_kernel()
{
    extern __shared__ uint32_t smu[];
    uint32_t* Ks = smu;                // [64][AP] tf32, K[key][d]
    uint32_t* Vs = smu + 64 * AP;      // [64][AP] tf32, V[key][d]
    uint32_t* Ps = smu + 2 * 64 * AP;  // [64][AP] tf32: Q at start, then P

    const int bh  = blockIdx.y;
    const int q0  = blockIdx.x * 64;
    const int tid = threadIdx.x;
    const int warp = tid >> 5;
    const int lane = tid & 31;
    const int g   = lane >> 2;     // groupID (0..7)
    const int tg  = lane & 3;      // thread-in-group
    const int mrow = warp * 16;    // warp's query-row base within tile

    const float* Qg = g_qh + (size_t)bh * SEQ * DK + (size_t)q0 * DK;
    const float* Kg = g_kh + (size_t)bh * SEQ * DK;
    const float* Vg = g_vh + (size_t)bh * SEQ * DK;

    const int lr0 = tid >> 4;        // 0..7
    const int lc  = (tid & 15) * 4;  // 0..60

    // Load Q tile (tf32) into Ps
#pragma unroll
    for (int rr = 0; rr < 64; rr += 8) {
        float4 qv = *(const float4*)&Qg[(size_t)(rr + lr0) * DK + lc];
        uint32_t* p = &Ps[(rr + lr0) * AP + lc];
        p[0] = f2tf(qv.x); p[1] = f2tf(qv.y);
        p[2] = f2tf(qv.z); p[3] = f2tf(qv.w);
    }
    __syncthreads();

    // Extract Q fragments into registers (m16 x k64 per warp)
    uint32_t qa[8][4];
#pragma unroll
    for (int ks = 0; ks < 8; ks++) {
        qa[ks][0] = Ps[(mrow + g    ) * AP + ks * 8 + tg];
        qa[ks][1] = Ps[(mrow + g + 8) * AP + ks * 8 + tg];
        qa[ks][2] = Ps[(mrow + g    ) * AP + ks * 8 + tg + 4];
        qa[ks][3] = Ps[(mrow + g + 8) * AP + ks * 8 + tg + 4];
    }

    float o[8][4];
#pragma unroll
    for (int nt = 0; nt < 8; nt++)
#pragma unroll
        for (int j = 0; j < 4; j++) o[nt][j] = 0.f;
    float m0 = -1e30f, m1 = -1e30f, l0 = 0.f, l1 = 0.f;

    for (int kt = 0; kt < SEQ / 64; kt++) {
        __syncthreads();   // all warps done with prev K/V (and Q frags read)
        {
            const float* Kt = Kg + (size_t)kt * 64 * DK;
            const float* Vt = Vg + (size_t)kt * 64 * DK;
#pragma unroll
            for (int rr = 0; rr < 64; rr += 8) {
                float4 kv = *(const float4*)&Kt[(size_t)(rr + lr0) * DK + lc];
                uint32_t* pk = &Ks[(rr + lr0) * AP + lc];
                pk[0] = f2tf(kv.x); pk[1] = f2tf(kv.y);
                pk[2] = f2tf(kv.z); pk[3] = f2tf(kv.w);
                float4 vv = *(const float4*)&Vt[(size_t)(rr + lr0) * DK + lc];
                uint32_t* pv = &Vs[(rr + lr0) * AP + lc];
                pv[0] = f2tf(vv.x); pv[1] = f2tf(vv.y);
                pv[2] = f2tf(vv.z); pv[3] = f2tf(vv.w);
            }
        }
        __syncthreads();

        // S = Q @ K^T  : s[nt] is m16n8 accumulator for keys nt*8..nt*8+7
        float s[8][4];
#pragma unroll
        for (int nt = 0; nt < 8; nt++)
#pragma unroll
            for (int j = 0; j < 4; j++) s[nt][j] = 0.f;

#pragma unroll
        for (int nt = 0; nt < 8; nt++) {
#pragma unroll
            for (int ks = 0; ks < 8; ks++) {
                uint32_t b0 = Ks[(nt * 8 + g) * AP + ks * 8 + tg];
                uint32_t b1 = Ks[(nt * 8 + g) * AP + ks * 8 + tg + 4];
                mma_tf32(s[nt], qa[ks], b0, b1);
            }
        }

        // Online softmax. Thread owns rows (mrow+g) via s[.][0..1] and
        // (mrow+g+8) via s[.][2..3]; reduce across the 4-lane tg group.
        float mx0 = -1e30f, mx1 = -1e30f;
#pragma unroll
        for (int nt = 0; nt < 8; nt++) {
            mx0 = fmaxf(mx0, fmaxf(s[nt][0], s[nt][1]));
            mx1 = fmaxf(mx1, fmaxf(s[nt][2], s[nt][3]));
        }
        mx0 = fmaxf(mx0, __shfl_xor_sync(0xffffffffu, mx0, 1));
        mx0 = fmaxf(mx0, __shfl_xor_sync(0xffffffffu, mx0, 2));
        mx1 = fmaxf(mx1, __shfl_xor_sync(0xffffffffu, mx1, 1));
        mx1 = fmaxf(mx1, __shfl_xor_sync(0xffffffffu, mx1, 2));

        const float mn0 = fmaxf(m0, mx0), mn1 = fmaxf(m1, mx1);
        const float c0 = __expf(m0 - mn0), c1 = __expf(m1 - mn1);
        m0 = mn0; m1 = mn1;

        float sum0 = 0.f, sum1 = 0.f;
#pragma unroll
        for (int nt = 0; nt < 8; nt++) {
            float p00 = __expf(s[nt][0] - m0);
            float p01 = __expf(s[nt][1] - m0);
            float p10 = __expf(s[nt][2] - m1);
            float p11 = __expf(s[nt][3] - m1);
            sum0 += p00 + p01;
            sum1 += p10 + p11;
            uint2 w0; w0.x = f2tf(p00); w0.y = f2tf(p01);
            *(uint2*)&Ps[(mrow + g    ) * AP + nt * 8 + 2 * tg] = w0;
            uint2 w1; w1.x = f2tf(p10); w1.y = f2tf(p11);
            *(uint2*)&Ps[(mrow + g + 8) * AP + nt * 8 + 2 * tg] = w1;
        }
        sum0 += __shfl_xor_sync(0xffffffffu, sum0, 1);
        sum0 += __shfl_xor_sync(0xffffffffu, sum0, 2);
        sum1 += __shfl_xor_sync(0xffffffffu, sum1, 1);
        sum1 += __shfl_xor_sync(0xffffffffu, sum1, 2);
        l0 = l0 * c0 + sum0;
        l1 = l1 * c1 + sum1;
#pragma unroll
        for (int nt = 0; nt < 8; nt++) {
            o[nt][0] *= c0; o[nt][1] *= c0;
            o[nt][2] *= c1; o[nt][3] *= c1;
        }
        __syncwarp();   // P writes visible within warp (P traffic is intra-warp)

        // O += P @ V
#pragma unroll
        for (int ks = 0; ks < 8; ks++) {
            uint32_t pa[4];
            pa[0] = Ps[(mrow + g    ) * AP + ks * 8 + tg];
            pa[1] = Ps[(mrow + g + 8) * AP + ks * 8 + tg];
            pa[2] = Ps[(mrow + g    ) * AP + ks * 8 + tg + 4];
            pa[3] = Ps[(mrow + g + 8) * AP + ks * 8 + tg + 4];
#pragma unroll
            for (int nt = 0; nt < 8; nt++) {
                uint32_t b0 = Vs[(ks * 8 + tg    ) * AP + nt * 8 + g];
                uint32_t b1 = Vs[(ks * 8 + tg + 4) * AP + nt * 8 + g];
                mma_tf32(o[nt], pa, b0, b1);
            }
        }
        __syncwarp();   // P reads done before next iteration overwrites
    }

    // Epilogue: normalize and write [B,S,D] (heads concatenated)
    const int bb = bh >> 3, hh = bh & 7;
    const float inv0 = 1.0f / l0, inv1 = 1.0f / l1;
    float* Og = g_att + ((size_t)bb * SEQ + q0) * DMODEL + hh * DK;
#pragma unroll
    for (int nt = 0; nt < 8; nt++) {
        float2 r0; r0.x = o[nt][0] * inv0; r0.y = o[nt][1] * inv0;
        *(float2*)&Og[(size_t)(mrow + g    ) * DMODEL + nt * 8 + 2 * tg] = r0;
        float2 r1; r1.x = o[nt][2] * inv1; r1.y = o[nt][3] * inv1;
        *(float2*)&Og[(size_t)(mrow + g + 8) * DMODEL + nt * 8 + 2 * tg] = r1;
    }
}

// ---------------------------------------------------------------------------
extern "C" void kernel_launch(void* const* d_in, const int* in_sizes, int n_in,
                              void* d_out, int out_size)
{
    const float* q  = (const float*)d_in[0];
    const float* k  = (const float*)d_in[1];
    const float* v  = (const float*)d_in[2];
    const float* wq = (const float*)d_in[3];
    const float* bq = (const float*)d_in[4];
    const float* wk = (const float*)d_in[5];
    const float* bk = (const float*)d_in[6];
    const float* wv = (const float*)d_in[7];
    const float* bv = (const float*)d_in[8];
    const float* wo = (const float*)d_in[9];
    const float* bo = (const float*)d_in[10];

    float *qh, *kh, *vh, *att;
    cudaGetSymbolAddress((void**)&qh,  g_qh);
    cudaGetSymbolAddress((void**)&kh,  g_kh);
    cudaGetSymbolAddress((void**)&vh,  g_vh);
    cudaGetSymbolAddress((void**)&att, g_att);

    cudaFuncSetAttribute(attn_mma_kernel,
                         cudaFuncAttributeMaxDynamicSharedMemorySize,
                         ATT_SMEM_BYTES);

    dim3 blk(256);
    dim3 gg(DMODEL / 128, MTOT / 128);   // (4, 64)

    // scale 1/sqrt(Dk) = 0.125 fused into Q projection
    gemm_bias_kernel<true><<<gg, blk>>>(q, wq, bq, qh, 0.125f);
    gemm_bias_kernel<true><<<gg, blk>>>(k, wk, bk, kh, 1.0f);
    gemm_bias_kernel<true><<<gg, blk>>>(v, wv, bv, vh, 1.0f);

    attn_mma_kernel<<<dim3(SEQ / 64, BATCH * NHEAD), 128, ATT_SMEM_BYTES>>>();

    gemm_bias_kernel<false><<<gg, blk>>>((const float*)att, wo, bo,
                                         (float*)d_out, 1.0f);
}

// round 3
// speedup vs baseline: 4.0240x; 1.7026x over previous
#include <cuda_runtime.h>
#include <cstdint>

#define DMODEL 512
#define NHEAD  8
#define DK     64
#define BATCH  2
#define SEQ    4096
#define MTOT   (BATCH*SEQ)   // 8192

// Scratch (static device arrays — no runtime allocation)
__device__ float g_qh[(size_t)BATCH*NHEAD*SEQ*DK];   // [B,H,S,Dk], tf32, pre-scaled 1/8
__device__ float g_kh[(size_t)BATCH*NHEAD*SEQ*DK];   // [B,H,S,Dk], tf32
__device__ float g_vh[(size_t)BATCH*NHEAD*SEQ*DK];   // [B,H,Dk,S] TRANSPOSED, tf32
__device__ float g_att[(size_t)MTOT*DMODEL];         // [B,S,D], tf32-rounded
__device__ float g_rq[(size_t)MTOT*DMODEL];          // tf32-rounded inputs
__device__ float g_rk[(size_t)MTOT*DMODEL];
__device__ float g_rv[(size_t)MTOT*DMODEL];
__device__ float g_rw[(size_t)4*DMODEL*DMODEL];      // tf32-rounded weights

// ---------------------------------------------------------------------------
__device__ __forceinline__ uint32_t f2tf(float f) {
    uint32_t u;
    asm("cvt.rna.tf32.f32 %0, %1;" : "=r"(u) : "f"(f));
    return u;
}
__device__ __forceinline__ float rnaf(float f) { return __uint_as_float(f2tf(f)); }

__device__ __forceinline__ void mma_tf32(float* d, const uint32_t* a,
                                         uint32_t b0, uint32_t b1) {
    asm volatile(
        "mma.sync.aligned.m16n8k8.row.col.f32.tf32.tf32.f32 "
        "{%0,%1,%2,%3}, {%4,%5,%6,%7}, {%8,%9}, {%0,%1,%2,%3};\n"
        : "+f"(d[0]), "+f"(d[1]), "+f"(d[2]), "+f"(d[3])
        : "r"(a[0]), "r"(a[1]), "r"(a[2]), "r"(a[3]), "r"(b0), "r"(b1));
}

__device__ __forceinline__ void cp16(uint32_t saddr, const void* g) {
    asm volatile("cp.async.cg.shared.global [%0], [%1], 16;\n"
                 :: "r"(saddr), "l"(g));
}
__device__ __forceinline__ void cpcommit() {
    asm volatile("cp.async.commit_group;\n");
}
template<int N> __device__ __forceinline__ void cpwait() {
    asm volatile("cp.async.wait_group %0;\n" :: "n"(N));
}

// ---------------------------------------------------------------------------
// Elementwise rna-round to tf32 (enables raw cp.async into tf32 mma)
// ---------------------------------------------------------------------------
__global__ void round_kernel(const float4* __restrict__ src,
                             float4* __restrict__ dst, int n4)
{
    for (int i = blockIdx.x * blockDim.x + threadIdx.x; i < n4;
         i += gridDim.x * blockDim.x) {
        float4 v = src[i];
        v.x = rnaf(v.x); v.y = rnaf(v.y); v.z = rnaf(v.z); v.w = rnaf(v.w);
        dst[i] = v;
    }
}

// ---------------------------------------------------------------------------
// tf32 tensor-core GEMM: Y = (X @ W^T + bias) * scale
// X:[8192,512] W:[512,512] row-major, both pre-rounded to tf32.
// Tile 128x128xK32, 256 thr (8 warps, 4Mx2N), cp.async double-buffered.
// LAYOUT: 0 = flat [M,N] fp32 (no round); 1 = [B,H,S,Dk] rounded;
//         2 = [B,H,Dk,S] transposed rounded (for V).
// ---------------------------------------------------------------------------
#define GP 36
#define GSTAGE (128*GP)
#define GEMM_SMEM (4*GSTAGE*4)   // 73728 B

template<int LAYOUT>
__global__ __launch_bounds__(256)
void gemm_tf32(const float* __restrict__ X, const float* __restrict__ W,
               const float* __restrict__ bias, float* __restrict__ Y,
               float scale)
{
    extern __shared__ float sm[];
    float* A = sm;
    float* B = sm + 2 * GSTAGE;
    const int m0 = blockIdx.y * 128, n0 = blockIdx.x * 128;
    const int tid = threadIdx.x, lane = tid & 31, warp = tid >> 5;
    const int g = lane >> 2, tg = lane & 3;
    const int wm = (warp & 3) * 32, wn = (warp >> 2) * 64;
    const uint32_t sA = (uint32_t)__cvta_generic_to_shared(A);
    const uint32_t sB = (uint32_t)__cvta_generic_to_shared(B);

#define G_ISSUE(st, k0)                                                        \
    {                                                                          \
        _Pragma("unroll")                                                      \
        for (int i = 0; i < 4; i++) {                                          \
            int c = tid + i * 256;                                             \
            int row = c >> 3, kc = (c & 7) * 4;                                \
            cp16(sA + ((st) * GSTAGE + row * GP + kc) * 4,                     \
                 X + (size_t)(m0 + row) * DMODEL + (k0) + kc);                 \
            cp16(sB + ((st) * GSTAGE + row * GP + kc) * 4,                     \
                 W + (size_t)(n0 + row) * DMODEL + (k0) + kc);                 \
        }                                                                      \
    }

    G_ISSUE(0, 0);  cpcommit();
    G_ISSUE(1, 32); cpcommit();

    float acc[2][8][4];
#pragma unroll
    for (int t = 0; t < 2; t++)
#pragma unroll
        for (int j = 0; j < 8; j++)
#pragma unroll
            for (int c = 0; c < 4; c++) acc[t][j][c] = 0.f;

    for (int kt = 0; kt < 16; kt++) {
        cpwait<1>();
        __syncthreads();
        const float* As = A + (kt & 1) * GSTAGE;
        const float* Bs = B + (kt & 1) * GSTAGE;
#pragma unroll
        for (int ks = 0; ks < 4; ks++) {
            const int k = ks * 8;
            uint32_t a[2][4];
#pragma unroll
            for (int t = 0; t < 2; t++) {
                const int r = wm + t * 16;
                a[t][0] = __float_as_uint(As[(r + g    ) * GP + k + tg]);
                a[t][1] = __float_as_uint(As[(r + g + 8) * GP + k + tg]);
                a[t][2] = __float_as_uint(As[(r + g    ) * GP + k + tg + 4]);
                a[t][3] = __float_as_uint(As[(r + g + 8) * GP + k + tg + 4]);
            }
#pragma unroll
            for (int j = 0; j < 8; j++) {
                uint32_t b0 = __float_as_uint(Bs[(wn + j * 8 + g) * GP + k + tg]);
                uint32_t b1 = __float_as_uint(Bs[(wn + j * 8 + g) * GP + k + tg + 4]);
                mma_tf32(acc[0][j], a[0], b0, b1);
                mma_tf32(acc[1][j], a[1], b0, b1);
            }
        }
        __syncthreads();
        if (kt + 2 < 16) { G_ISSUE(kt & 1, (kt + 2) * 32); }
        cpcommit();
    }

#pragma unroll
    for (int t = 0; t < 2; t++) {
#pragma unroll
        for (int rr = 0; rr < 2; rr++) {
            const int r = m0 + wm + t * 16 + g + rr * 8;
            const int bb = r >> 12, ss = r & 4095;
#pragma unroll
            for (int j = 0; j < 8; j++) {
                const int n = n0 + wn + j * 8 + 2 * tg;
                float2 bi = *(const float2*)&bias[n];
                float v0 = (acc[t][j][rr * 2 + 0] + bi.x) * scale;
                float v1 = (acc[t][j][rr * 2 + 1] + bi.y) * scale;
                if (LAYOUT == 0) {
                    *(float2*)&Y[(size_t)r * DMODEL + n] = make_float2(v0, v1);
                } else if (LAYOUT == 1) {
                    const int h = n >> 6, d = n & 63;
                    *(float2*)&Y[(((size_t)(bb * NHEAD + h)) * SEQ + ss) * DK + d]
                        = make_float2(rnaf(v0), rnaf(v1));
                } else {
                    const int h = n >> 6, d = n & 63;
                    Y[(((size_t)(bb * NHEAD + h)) * DK + d    ) * SEQ + ss] = rnaf(v0);
                    Y[(((size_t)(bb * NHEAD + h)) * DK + d + 1) * SEQ + ss] = rnaf(v1);
                }
            }
        }
    }
#undef G_ISSUE
}

// ---------------------------------------------------------------------------
// tf32 flash attention, 128-query CTA tile, 4 warps x 32 rows (2 m16 halves).
// K/V double-buffered via cp.async (pre-rounded tf32 in gmem, V transposed).
// K/V B-fragments amortized across both halves. All frag LDS conflict-free.
// ---------------------------------------------------------------------------
#define AP 68
#define KVT (64*AP)
#define ATT_SMEM ((4*KVT + 128*AP)*4)   // 104448 B

__global__ __launch_bounds__(128)
void attn_kernel()
{
    extern __shared__ float sm[];
    float* Kb = sm;              // [2][64][AP]  K[key][d]
    float* Vb = sm + 2 * KVT;    // [2][64][AP]  V^T[d][key]
    float* Pb = sm + 4 * KVT;    // [128][AP]    Q then P (warp-private rows)

    const int bh = blockIdx.y, q0 = blockIdx.x * 128;
    const int tid = threadIdx.x, lane = tid & 31, warp = tid >> 5;
    const int g = lane >> 2, tg = lane & 3;
    const int w32 = warp * 32;

    const float* Qg = g_qh + (size_t)bh * SEQ * DK + (size_t)q0 * DK;
    const float* Kg = g_kh + (size_t)bh * SEQ * DK;
    const float* Vg = g_vh + (size_t)bh * DK * SEQ;

    const uint32_t sK = (uint32_t)__cvta_generic_to_shared(Kb);
    const uint32_t sV = (uint32_t)__cvta_generic_to_shared(Vb);
    const uint32_t sP = (uint32_t)__cvta_generic_to_shared(Pb);

    // Q tile: 128 rows x 64 = 2048 16B-chunks
#pragma unroll
    for (int i = 0; i < 16; i++) {
        int c = tid + i * 128;
        int row = c >> 4, kc = (c & 15) * 4;
        cp16(sP + (row * AP + kc) * 4, Qg + (size_t)row * DK + kc);
    }
    cpcommit();

#define KV_ISSUE(st, ktile)                                                    \
    {                                                                          \
        _Pragma("unroll")                                                      \
        for (int i = 0; i < 16; i++) {                                         \
            int c = tid + i * 128;                                             \
            int r = (c >> 4) & 63, kc = (c & 15) * 4;                          \
            if (c < 1024)                                                      \
                cp16(sK + ((st) * KVT + r * AP + kc) * 4,                      \
                     Kg + ((size_t)(ktile) * 64 + r) * DK + kc);               \
            else                                                               \
                cp16(sV + ((st) * KVT + r * AP + kc) * 4,                      \
                     Vg + (size_t)r * SEQ + (ktile) * 64 + kc);                \
        }                                                                      \
    }

    KV_ISSUE(0, 0); cpcommit();
    KV_ISSUE(1, 1); cpcommit();

    cpwait<2>();
    __syncthreads();

    // Q fragments (2 halves x k64)
    uint32_t qa[2][8][4];
#pragma unroll
    for (int h = 0; h < 2; h++) {
        const int mr = w32 + h * 16;
#pragma unroll
        for (int ks = 0; ks < 8; ks++) {
            qa[h][ks][0] = __float_as_uint(Pb[(mr + g    ) * AP + ks * 8 + tg]);
            qa[h][ks][1] = __float_as_uint(Pb[(mr + g + 8) * AP + ks * 8 + tg]);
            qa[h][ks][2] = __float_as_uint(Pb[(mr + g    ) * AP + ks * 8 + tg + 4]);
            qa[h][ks][3] = __float_as_uint(Pb[(mr + g + 8) * AP + ks * 8 + tg + 4]);
        }
    }

    float o[2][8][4];
    float m[2][2], l[2][2];
#pragma unroll
    for (int h = 0; h < 2; h++) {
        m[h][0] = -1e30f; m[h][1] = -1e30f; l[h][0] = 0.f; l[h][1] = 0.f;
#pragma unroll
        for (int nt = 0; nt < 8; nt++)
#pragma unroll
            for (int c = 0; c < 4; c++) o[h][nt][c] = 0.f;
    }

    for (int kt = 0; kt < SEQ / 64; kt++) {
        cpwait<1>();
        __syncthreads();
        const float* Ks = Kb + (kt & 1) * KVT;
        const float* Vs = Vb + (kt & 1) * KVT;

        // S = Q @ K^T for both halves (K fragments shared)
        float sc[2][8][4];
#pragma unroll
        for (int h = 0; h < 2; h++)
#pragma unroll
            for (int nt = 0; nt < 8; nt++)
#pragma unroll
                for (int c = 0; c < 4; c++) sc[h][nt][c] = 0.f;

#pragma unroll
        for (int nt = 0; nt < 8; nt++) {
#pragma unroll
            for (int ks = 0; ks < 8; ks++) {
                uint32_t b0 = __float_as_uint(Ks[(nt * 8 + g) * AP + ks * 8 + tg]);
                uint32_t b1 = __float_as_uint(Ks[(nt * 8 + g) * AP + ks * 8 + tg + 4]);
                mma_tf32(sc[0][nt], qa[0][ks], b0, b1);
                mma_tf32(sc[1][nt], qa[1][ks], b0, b1);
            }
        }

        // Online softmax per half
#pragma unroll
        for (int h = 0; h < 2; h++) {
            float mx0 = -1e30f, mx1 = -1e30f;
#pragma unroll
            for (int nt = 0; nt < 8; nt++) {
                mx0 = fmaxf(mx0, fmaxf(sc[h][nt][0], sc[h][nt][1]));
                mx1 = fmaxf(mx1, fmaxf(sc[h][nt][2], sc[h][nt][3]));
            }
            mx0 = fmaxf(mx0, __shfl_xor_sync(0xffffffffu, mx0, 1));
            mx0 = fmaxf(mx0, __shfl_xor_sync(0xffffffffu, mx0, 2));
            mx1 = fmaxf(mx1, __shfl_xor_sync(0xffffffffu, mx1, 1));
            mx1 = fmaxf(mx1, __shfl_xor_sync(0xffffffffu, mx1, 2));

            const float mn0 = fmaxf(m[h][0], mx0), mn1 = fmaxf(m[h][1], mx1);
            const float c0 = __expf(m[h][0] - mn0), c1 = __expf(m[h][1] - mn1);
            m[h][0] = mn0; m[h][1] = mn1;

            float s0 = 0.f, s1 = 0.f;
            const int rA = w32 + h * 16 + g;
#pragma unroll
            for (int nt = 0; nt < 8; nt++) {
                float p00 = __expf(sc[h][nt][0] - mn0);
                float p01 = __expf(sc[h][nt][1] - mn0);
                float p10 = __expf(sc[h][nt][2] - mn1);
                float p11 = __expf(sc[h][nt][3] - mn1);
                s0 += p00 + p01;
                s1 += p10 + p11;
                *(float2*)&Pb[(rA    ) * AP + nt * 8 + 2 * tg]
                    = make_float2(rnaf(p00), rnaf(p01));
                *(float2*)&Pb[(rA + 8) * AP + nt * 8 + 2 * tg]
                    = make_float2(rnaf(p10), rnaf(p11));
            }
            s0 += __shfl_xor_sync(0xffffffffu, s0, 1);
            s0 += __shfl_xor_sync(0xffffffffu, s0, 2);
            s1 += __shfl_xor_sync(0xffffffffu, s1, 1);
            s1 += __shfl_xor_sync(0xffffffffu, s1, 2);
            l[h][0] = l[h][0] * c0 + s0;
            l[h][1] = l[h][1] * c1 + s1;
#pragma unroll
            for (int nt = 0; nt < 8; nt++) {
                o[h][nt][0] *= c0; o[h][nt][1] *= c0;
                o[h][nt][2] *= c1; o[h][nt][3] *= c1;
            }
        }
        __syncwarp();   // P rows are warp-private

        // O += P @ V (V fragments shared across halves)
#pragma unroll
        for (int ks = 0; ks < 8; ks++) {
            uint32_t pa[2][4];
#pragma unroll
            for (int h = 0; h < 2; h++) {
                const int mr = w32 + h * 16;
                pa[h][0] = __float_as_uint(Pb[(mr + g    ) * AP + ks * 8 + tg]);
                pa[h][1] = __float_as_uint(Pb[(mr + g + 8) * AP + ks * 8 + tg]);
                pa[h][2] = __float_as_uint(Pb[(mr + g    ) * AP + ks * 8 + tg + 4]);
                pa[h][3] = __float_as_uint(Pb[(mr + g + 8) * AP + ks * 8 + tg + 4]);
            }
#pragma unroll
            for (int nt = 0; nt < 8; nt++) {
                uint32_t b0 = __float_as_uint(Vs[(nt * 8 + g) * AP + ks * 8 + tg]);
                uint32_t b1 = __float_as_uint(Vs[(nt * 8 + g) * AP + ks * 8 + tg + 4]);
                mma_tf32(o[0][nt], pa[0], b0, b1);
                mma_tf32(o[1][nt], pa[1], b0, b1);
            }
        }
        __syncthreads();   // all warps done with stage (kt&1) before refill
        if (kt + 2 < SEQ / 64) { KV_ISSUE(kt & 1, kt + 2); }
        cpcommit();
    }

    // Epilogue: normalize, round (feeds tf32 O-GEMM), write [B,S,D]
    const int bb = bh >> 3, hh = bh & 7;
    float* Og = g_att + ((size_t)bb * SEQ + q0) * DMODEL + hh * DK;
#pragma unroll
    for (int h = 0; h < 2; h++) {
#pragma unroll
        for (int rr = 0; rr < 2; rr++) {
            const float inv = 1.0f / l[h][rr];
            const int row = w32 + h * 16 + g + rr * 8;
#pragma unroll
            for (int nt = 0; nt < 8; nt++) {
                *(float2*)&Og[(size_t)row * DMODEL + nt * 8 + 2 * tg]
                    = make_float2(rnaf(o[h][nt][rr * 2 + 0] * inv),
                                  rnaf(o[h][nt][rr * 2 + 1] * inv));
            }
        }
    }
#undef KV_ISSUE
}

// ---------------------------------------------------------------------------
extern "C" void kernel_launch(void* const* d_in, const int* in_sizes, int n_in,
                              void* d_out, int out_size)
{
    const float* q  = (const float*)d_in[0];
    const float* k  = (const float*)d_in[1];
    const float* v  = (const float*)d_in[2];
    const float* wq = (const float*)d_in[3];
    const float* bq = (const float*)d_in[4];
    const float* wk = (const float*)d_in[5];
    const float* bk = (const float*)d_in[6];
    const float* wv = (const float*)d_in[7];
    const float* bv = (const float*)d_in[8];
    const float* wo = (const float*)d_in[9];
    const float* bo = (const float*)d_in[10];

    float *qh, *kh, *vh, *att, *rq, *rk, *rv, *rw;
    cudaGetSymbolAddress((void**)&qh,  g_qh);
    cudaGetSymbolAddress((void**)&kh,  g_kh);
    cudaGetSymbolAddress((void**)&vh,  g_vh);
    cudaGetSymbolAddress((void**)&att, g_att);
    cudaGetSymbolAddress((void**)&rq,  g_rq);
    cudaGetSymbolAddress((void**)&rk,  g_rk);
    cudaGetSymbolAddress((void**)&rv,  g_rv);
    cudaGetSymbolAddress((void**)&rw,  g_rw);

    cudaFuncSetAttribute(gemm_tf32<0>,
        cudaFuncAttributeMaxDynamicSharedMemorySize, GEMM_SMEM);
    cudaFuncSetAttribute(gemm_tf32<1>,
        cudaFuncAttributeMaxDynamicSharedMemorySize, GEMM_SMEM);
    cudaFuncSetAttribute(gemm_tf32<2>,
        cudaFuncAttributeMaxDynamicSharedMemorySize, GEMM_SMEM);
    cudaFuncSetAttribute(attn_kernel,
        cudaFuncAttributeMaxDynamicSharedMemorySize, ATT_SMEM);

    const int DD = DMODEL * DMODEL;
    const int n4x = MTOT * DMODEL / 4;   // 1048576
    const int n4w = DD / 4;              // 65536

    // tf32 pre-rounding
    round_kernel<<<512, 256>>>((const float4*)q,  (float4*)rq, n4x);
    round_kernel<<<512, 256>>>((const float4*)k,  (float4*)rk, n4x);
    round_kernel<<<512, 256>>>((const float4*)v,  (float4*)rv, n4x);
    round_kernel<<<128, 256>>>((const float4*)wq, (float4*)(rw + 0 * DD), n4w);
    round_kernel<<<128, 256>>>((const float4*)wk, (float4*)(rw + 1 * DD), n4w);
    round_kernel<<<128, 256>>>((const float4*)wv, (float4*)(rw + 2 * DD), n4w);
    round_kernel<<<128, 256>>>((const float4*)wo, (float4*)(rw + 3 * DD), n4w);

    dim3 gg(DMODEL / 128, MTOT / 128);   // (4, 64)
    // scale 1/sqrt(Dk)=0.125 fused into Q projection
    gemm_tf32<1><<<gg, 256, GEMM_SMEM>>>(rq, rw + 0 * DD, bq, qh, 0.125f);
    gemm_tf32<1><<<gg, 256, GEMM_SMEM>>>(rk, rw + 1 * DD, bk, kh, 1.0f);
    gemm_tf32<2><<<gg, 256, GEMM_SMEM>>>(rv, rw + 2 * DD, bv, vh, 1.0f);

    attn_kernel<<<dim3(SEQ / 128, BATCH * NHEAD), 128, ATT_SMEM>>>();

    gemm_tf32<0><<<gg, 256, GEMM_SMEM>>>(att, rw + 3 * DD, bo,
                                         (float*)d_out, 1.0f);
}

// round 4
// speedup vs baseline: 4.0516x; 1.0069x over previous
#include <cuda_runtime.h>
#include <cstdint>

#define DMODEL 512
#define NHEAD  8
#define DK     64
#define BATCH  2
#define SEQ    4096
#define MTOT   (BATCH*SEQ)   // 8192

// Scratch (static device arrays — no runtime allocation)
__device__ float g_qh[(size_t)BATCH*NHEAD*SEQ*DK];   // [B,H,S,Dk], tf32, pre-scaled 1/8
__device__ float g_kh[(size_t)BATCH*NHEAD*SEQ*DK];   // [B,H,S,Dk], tf32
__device__ float g_vh[(size_t)BATCH*NHEAD*SEQ*DK];   // [B,H,Dk,S] TRANSPOSED, tf32
__device__ float g_att[(size_t)MTOT*DMODEL];         // [B,S,D], tf32-rounded
__device__ float g_rq[(size_t)MTOT*DMODEL];          // tf32-rounded inputs
__device__ float g_rk[(size_t)MTOT*DMODEL];
__device__ float g_rv[(size_t)MTOT*DMODEL];
__device__ float g_rw[(size_t)4*DMODEL*DMODEL];      // tf32-rounded weights

// ---------------------------------------------------------------------------
__device__ __forceinline__ uint32_t f2tf(float f) {
    uint32_t u;
    asm("cvt.rna.tf32.f32 %0, %1;" : "=r"(u) : "f"(f));
    return u;
}
__device__ __forceinline__ float rnaf(float f) { return __uint_as_float(f2tf(f)); }

__device__ __forceinline__ void mma_tf32(float* d, const uint32_t* a,
                                         uint32_t b0, uint32_t b1) {
    asm volatile(
        "mma.sync.aligned.m16n8k8.row.col.f32.tf32.tf32.f32 "
        "{%0,%1,%2,%3}, {%4,%5,%6,%7}, {%8,%9}, {%0,%1,%2,%3};\n"
        : "+f"(d[0]), "+f"(d[1]), "+f"(d[2]), "+f"(d[3])
        : "r"(a[0]), "r"(a[1]), "r"(a[2]), "r"(a[3]), "r"(b0), "r"(b1));
}

__device__ __forceinline__ void cp16(uint32_t saddr, const void* g) {
    asm volatile("cp.async.cg.shared.global [%0], [%1], 16;\n"
                 :: "r"(saddr), "l"(g));
}
__device__ __forceinline__ void cpcommit() {
    asm volatile("cp.async.commit_group;\n");
}
template<int N> __device__ __forceinline__ void cpwait() {
    asm volatile("cp.async.wait_group %0;\n" :: "n"(N));
}

// ---------------------------------------------------------------------------
// Batched rna-round to tf32: blockIdx.y selects src/dst pair.
// ---------------------------------------------------------------------------
__global__ void round3_kernel(const float4* __restrict__ s0,
                              const float4* __restrict__ s1,
                              const float4* __restrict__ s2,
                              float4* __restrict__ d0,
                              float4* __restrict__ d1,
                              float4* __restrict__ d2, int n4)
{
    const float4* s = (blockIdx.y == 0) ? s0 : (blockIdx.y == 1) ? s1 : s2;
    float4*       d = (blockIdx.y == 0) ? d0 : (blockIdx.y == 1) ? d1 : d2;
    for (int i = blockIdx.x * blockDim.x + threadIdx.x; i < n4;
         i += gridDim.x * blockDim.x) {
        float4 v = s[i];
        v.x = rnaf(v.x); v.y = rnaf(v.y); v.z = rnaf(v.z); v.w = rnaf(v.w);
        d[i] = v;
    }
}

__global__ void round4_kernel(const float4* __restrict__ s0,
                              const float4* __restrict__ s1,
                              const float4* __restrict__ s2,
                              const float4* __restrict__ s3,
                              float4* __restrict__ dst, int n4)
{
    const float4* s = (blockIdx.y == 0) ? s0 : (blockIdx.y == 1) ? s1
                    : (blockIdx.y == 2) ? s2 : s3;
    float4* d = dst + (size_t)blockIdx.y * n4;
    for (int i = blockIdx.x * blockDim.x + threadIdx.x; i < n4;
         i += gridDim.x * blockDim.x) {
        float4 v = s[i];
        v.x = rnaf(v.x); v.y = rnaf(v.y); v.z = rnaf(v.z); v.w = rnaf(v.w);
        d[i] = v;
    }
}

// ---------------------------------------------------------------------------
// tf32 tensor-core GEMM: Y = (X @ W^T + bias) * scale   (unchanged from R3)
// ---------------------------------------------------------------------------
#define GP 36
#define GSTAGE (128*GP)
#define GEMM_SMEM (4*GSTAGE*4)   // 73728 B

template<int LAYOUT>
__global__ __launch_bounds__(256)
void gemm_tf32(const float* __restrict__ X, const float* __restrict__ W,
               const float* __restrict__ bias, float* __restrict__ Y,
               float scale)
{
    extern __shared__ float sm[];
    float* A = sm;
    float* B = sm + 2 * GSTAGE;
    const int m0 = blockIdx.y * 128, n0 = blockIdx.x * 128;
    const int tid = threadIdx.x, lane = tid & 31, warp = tid >> 5;
    const int g = lane >> 2, tg = lane & 3;
    const int wm = (warp & 3) * 32, wn = (warp >> 2) * 64;
    const uint32_t sA = (uint32_t)__cvta_generic_to_shared(A);
    const uint32_t sB = (uint32_t)__cvta_generic_to_shared(B);

#define G_ISSUE(st, k0)                                                        \
    {                                                                          \
        _Pragma("unroll")                                                      \
        for (int i = 0; i < 4; i++) {                                          \
            int c = tid + i * 256;                                             \
            int row = c >> 3, kc = (c & 7) * 4;                                \
            cp16(sA + ((st) * GSTAGE + row * GP + kc) * 4,                     \
                 X + (size_t)(m0 + row) * DMODEL + (k0) + kc);                 \
            cp16(sB + ((st) * GSTAGE + row * GP + kc) * 4,                     \
                 W + (size_t)(n0 + row) * DMODEL + (k0) + kc);                 \
        }                                                                      \
    }

    G_ISSUE(0, 0);  cpcommit();
    G_ISSUE(1, 32); cpcommit();

    float acc[2][8][4];
#pragma unroll
    for (int t = 0; t < 2; t++)
#pragma unroll
        for (int j = 0; j < 8; j++)
#pragma unroll
            for (int c = 0; c < 4; c++) acc[t][j][c] = 0.f;

    for (int kt = 0; kt < 16; kt++) {
        cpwait<1>();
        __syncthreads();
        const float* As = A + (kt & 1) * GSTAGE;
        const float* Bs = B + (kt & 1) * GSTAGE;
#pragma unroll
        for (int ks = 0; ks < 4; ks++) {
            const int k = ks * 8;
            uint32_t a[2][4];
#pragma unroll
            for (int t = 0; t < 2; t++) {
                const int r = wm + t * 16;
                a[t][0] = __float_as_uint(As[(r + g    ) * GP + k + tg]);
                a[t][1] = __float_as_uint(As[(r + g + 8) * GP + k + tg]);
                a[t][2] = __float_as_uint(As[(r + g    ) * GP + k + tg + 4]);
                a[t][3] = __float_as_uint(As[(r + g + 8) * GP + k + tg + 4]);
            }
#pragma unroll
            for (int j = 0; j < 8; j++) {
                uint32_t b0 = __float_as_uint(Bs[(wn + j * 8 + g) * GP + k + tg]);
                uint32_t b1 = __float_as_uint(Bs[(wn + j * 8 + g) * GP + k + tg + 4]);
                mma_tf32(acc[0][j], a[0], b0, b1);
                mma_tf32(acc[1][j], a[1], b0, b1);
            }
        }
        __syncthreads();
        if (kt + 2 < 16) { G_ISSUE(kt & 1, (kt + 2) * 32); }
        cpcommit();
    }

#pragma unroll
    for (int t = 0; t < 2; t++) {
#pragma unroll
        for (int rr = 0; rr < 2; rr++) {
            const int r = m0 + wm + t * 16 + g + rr * 8;
            const int bb = r >> 12, ss = r & 4095;
#pragma unroll
            for (int j = 0; j < 8; j++) {
                const int n = n0 + wn + j * 8 + 2 * tg;
                float2 bi = *(const float2*)&bias[n];
                float v0 = (acc[t][j][rr * 2 + 0] + bi.x) * scale;
                float v1 = (acc[t][j][rr * 2 + 1] + bi.y) * scale;
                if (LAYOUT == 0) {
                    *(float2*)&Y[(size_t)r * DMODEL + n] = make_float2(v0, v1);
                } else if (LAYOUT == 1) {
                    const int h = n >> 6, d = n & 63;
                    *(float2*)&Y[(((size_t)(bb * NHEAD + h)) * SEQ + ss) * DK + d]
                        = make_float2(rnaf(v0), rnaf(v1));
                } else {
                    const int h = n >> 6, d = n & 63;
                    Y[(((size_t)(bb * NHEAD + h)) * DK + d    ) * SEQ + ss] = rnaf(v0);
                    Y[(((size_t)(bb * NHEAD + h)) * DK + d + 1) * SEQ + ss] = rnaf(v1);
                }
            }
        }
    }
#undef G_ISSUE
}

// ---------------------------------------------------------------------------
// tf32 flash attention: 256 threads (8 warps) x 256 query rows per CTA,
// 32 rows/warp (2 m16 halves, K/V B-fragments amortized 2x).
// K/V 64-key tiles double-buffered via cp.async; V transposed in gmem.
// ---------------------------------------------------------------------------
#define AP 68
#define KVT (64*AP)
#define QROWS 256
#define ATT_SMEM ((4*KVT + QROWS*AP)*4)   // 139264 B

__global__ __launch_bounds__(256)
void attn_kernel()
{
    extern __shared__ float sm[];
    float* Kb = sm;              // [2][64][AP]  K[key][d]
    float* Vb = sm + 2 * KVT;    // [2][64][AP]  V^T[d][key]
    float* Pb = sm + 4 * KVT;    // [256][AP]    Q then P (warp-private rows)

    const int bh = blockIdx.y, q0 = blockIdx.x * QROWS;
    const int tid = threadIdx.x, lane = tid & 31, warp = tid >> 5;
    const int g = lane >> 2, tg = lane & 3;
    const int w32 = warp * 32;

    const float* Qg = g_qh + (size_t)bh * SEQ * DK + (size_t)q0 * DK;
    const float* Kg = g_kh + (size_t)bh * SEQ * DK;
    const float* Vg = g_vh + (size_t)bh * DK * SEQ;

    const uint32_t sK = (uint32_t)__cvta_generic_to_shared(Kb);
    const uint32_t sV = (uint32_t)__cvta_generic_to_shared(Vb);
    const uint32_t sP = (uint32_t)__cvta_generic_to_shared(Pb);

    // Q tile: 256 rows x 64 = 4096 16B-chunks over 256 threads
#pragma unroll
    for (int i = 0; i < 16; i++) {
        int c = tid + i * 256;
        int row = c >> 4, kc = (c & 15) * 4;
        cp16(sP + (row * AP + kc) * 4, Qg + (size_t)row * DK + kc);
    }
    cpcommit();

#define KV_ISSUE(st, ktile)                                                    \
    {                                                                          \
        _Pragma("unroll")                                                      \
        for (int i = 0; i < 8; i++) {                                          \
            int c = tid + i * 256;                                             \
            int r = (c >> 4) & 63, kc = (c & 15) * 4;                          \
            if (c < 1024)                                                      \
                cp16(sK + ((st) * KVT + r * AP + kc) * 4,                      \
                     Kg + ((size_t)(ktile) * 64 + r) * DK + kc);               \
            else                                                               \
                cp16(sV + ((st) * KVT + r * AP + kc) * 4,                      \
                     Vg + (size_t)r * SEQ + (ktile) * 64 + kc);                \
        }                                                                      \
    }

    KV_ISSUE(0, 0); cpcommit();
    KV_ISSUE(1, 1); cpcommit();

    cpwait<2>();
    __syncthreads();

    // Q fragments (2 halves x k64)
    uint32_t qa[2][8][4];
#pragma unroll
    for (int h = 0; h < 2; h++) {
        const int mr = w32 + h * 16;
#pragma unroll
        for (int ks = 0; ks < 8; ks++) {
            qa[h][ks][0] = __float_as_uint(Pb[(mr + g    ) * AP + ks * 8 + tg]);
            qa[h][ks][1] = __float_as_uint(Pb[(mr + g + 8) * AP + ks * 8 + tg]);
            qa[h][ks][2] = __float_as_uint(Pb[(mr + g    ) * AP + ks * 8 + tg + 4]);
            qa[h][ks][3] = __float_as_uint(Pb[(mr + g + 8) * AP + ks * 8 + tg + 4]);
        }
    }

    float o[2][8][4];
    float m[2][2], l[2][2];
#pragma unroll
    for (int h = 0; h < 2; h++) {
        m[h][0] = -1e30f; m[h][1] = -1e30f; l[h][0] = 0.f; l[h][1] = 0.f;
#pragma unroll
        for (int nt = 0; nt < 8; nt++)
#pragma unroll
            for (int c = 0; c < 4; c++) o[h][nt][c] = 0.f;
    }

    for (int kt = 0; kt < SEQ / 64; kt++) {
        cpwait<1>();
        __syncthreads();
        const float* Ks = Kb + (kt & 1) * KVT;
        const float* Vs = Vb + (kt & 1) * KVT;

        // S = Q @ K^T for both halves (K fragments shared)
        float sc[2][8][4];
#pragma unroll
        for (int h = 0; h < 2; h++)
#pragma unroll
            for (int nt = 0; nt < 8; nt++)
#pragma unroll
                for (int c = 0; c < 4; c++) sc[h][nt][c] = 0.f;

#pragma unroll
        for (int nt = 0; nt < 8; nt++) {
#pragma unroll
            for (int ks = 0; ks < 8; ks++) {
                uint32_t b0 = __float_as_uint(Ks[(nt * 8 + g) * AP + ks * 8 + tg]);
                uint32_t b1 = __float_as_uint(Ks[(nt * 8 + g) * AP + ks * 8 + tg + 4]);
                mma_tf32(sc[0][nt], qa[0][ks], b0, b1);
                mma_tf32(sc[1][nt], qa[1][ks], b0, b1);
            }
        }

        // Online softmax per half
#pragma unroll
        for (int h = 0; h < 2; h++) {
            float mx0 = -1e30f, mx1 = -1e30f;
#pragma unroll
            for (int nt = 0; nt < 8; nt++) {
                mx0 = fmaxf(mx0, fmaxf(sc[h][nt][0], sc[h][nt][1]));
                mx1 = fmaxf(mx1, fmaxf(sc[h][nt][2], sc[h][nt][3]));
            }
            mx0 = fmaxf(mx0, __shfl_xor_sync(0xffffffffu, mx0, 1));
            mx0 = fmaxf(mx0, __shfl_xor_sync(0xffffffffu, mx0, 2));
            mx1 = fmaxf(mx1, __shfl_xor_sync(0xffffffffu, mx1, 1));
            mx1 = fmaxf(mx1, __shfl_xor_sync(0xffffffffu, mx1, 2));

            const float mn0 = fmaxf(m[h][0], mx0), mn1 = fmaxf(m[h][1], mx1);
            const float c0 = __expf(m[h][0] - mn0), c1 = __expf(m[h][1] - mn1);
            m[h][0] = mn0; m[h][1] = mn1;

            float s0 = 0.f, s1 = 0.f;
            const int rA = w32 + h * 16 + g;
#pragma unroll
            for (int nt = 0; nt < 8; nt++) {
                float p00 = __expf(sc[h][nt][0] - mn0);
                float p01 = __expf(sc[h][nt][1] - mn0);
                float p10 = __expf(sc[h][nt][2] - mn1);
                float p11 = __expf(sc[h][nt][3] - mn1);
                s0 += p00 + p01;
                s1 += p10 + p11;
                *(float2*)&Pb[(rA    ) * AP + nt * 8 + 2 * tg]
                    = make_float2(rnaf(p00), rnaf(p01));
                *(float2*)&Pb[(rA + 8) * AP + nt * 8 + 2 * tg]
                    = make_float2(rnaf(p10), rnaf(p11));
            }
            s0 += __shfl_xor_sync(0xffffffffu, s0, 1);
            s0 += __shfl_xor_sync(0xffffffffu, s0, 2);
            s1 += __shfl_xor_sync(0xffffffffu, s1, 1);
            s1 += __shfl_xor_sync(0xffffffffu, s1, 2);
            l[h][0] = l[h][0] * c0 + s0;
            l[h][1] = l[h][1] * c1 + s1;
#pragma unroll
            for (int nt = 0; nt < 8; nt++) {
                o[h][nt][0] *= c0; o[h][nt][1] *= c0;
                o[h][nt][2] *= c1; o[h][nt][3] *= c1;
            }
        }
        __syncwarp();   // P rows are warp-private

        // O += P @ V (V fragments shared across halves)
#pragma unroll
        for (int ks = 0; ks < 8; ks++) {
            uint32_t pa[2][4];
#pragma unroll
            for (int h = 0; h < 2; h++) {
                const int mr = w32 + h * 16;
                pa[h][0] = __float_as_uint(Pb[(mr + g    ) * AP + ks * 8 + tg]);
                pa[h][1] = __float_as_uint(Pb[(mr + g + 8) * AP + ks * 8 + tg]);
                pa[h][2] = __float_as_uint(Pb[(mr + g    ) * AP + ks * 8 + tg + 4]);
                pa[h][3] = __float_as_uint(Pb[(mr + g + 8) * AP + ks * 8 + tg + 4]);
            }
#pragma unroll
            for (int nt = 0; nt < 8; nt++) {
                uint32_t b0 = __float_as_uint(Vs[(nt * 8 + g) * AP + ks * 8 + tg]);
                uint32_t b1 = __float_as_uint(Vs[(nt * 8 + g) * AP + ks * 8 + tg + 4]);
                mma_tf32(o[0][nt], pa[0], b0, b1);
                mma_tf32(o[1][nt], pa[1], b0, b1);
            }
        }
        __syncthreads();   // all warps done with stage (kt&1) before refill
        if (kt + 2 < SEQ / 64) { KV_ISSUE(kt & 1, kt + 2); }
        cpcommit();
    }

    // Epilogue: normalize, round (feeds tf32 O-GEMM), write [B,S,D]
    const int bb = bh >> 3, hh = bh & 7;
    float* Og = g_att + ((size_t)bb * SEQ + q0) * DMODEL + hh * DK;
#pragma unroll
    for (int h = 0; h < 2; h++) {
#pragma unroll
        for (int rr = 0; rr < 2; rr++) {
            const float inv = 1.0f / l[h][rr];
            const int row = w32 + h * 16 + g + rr * 8;
#pragma unroll
            for (int nt = 0; nt < 8; nt++) {
                *(float2*)&Og[(size_t)row * DMODEL + nt * 8 + 2 * tg]
                    = make_float2(rnaf(o[h][nt][rr * 2 + 0] * inv),
                                  rnaf(o[h][nt][rr * 2 + 1] * inv));
            }
        }
    }
#undef KV_ISSUE
}

// ---------------------------------------------------------------------------
extern "C" void kernel_launch(void* const* d_in, const int* in_sizes, int n_in,
                              void* d_out, int out_size)
{
    const float* q  = (const float*)d_in[0];
    const float* k  = (const float*)d_in[1];
    const float* v  = (const float*)d_in[2];
    const float* wq = (const float*)d_in[3];
    const float* bq = (const float*)d_in[4];
    const float* wk = (const float*)d_in[5];
    const float* bk = (const float*)d_in[6];
    const float* wv = (const float*)d_in[7];
    const float* bv = (const float*)d_in[8];
    const float* wo = (const float*)d_in[9];
    const float* bo = (const float*)d_in[10];

    float *qh, *kh, *vh, *att, *rq, *rk, *rv, *rw;
    cudaGetSymbolAddress((void**)&qh,  g_qh);
    cudaGetSymbolAddress((void**)&kh,  g_kh);
    cudaGetSymbolAddress((void**)&vh,  g_vh);
    cudaGetSymbolAddress((void**)&att, g_att);
    cudaGetSymbolAddress((void**)&rq,  g_rq);
    cudaGetSymbolAddress((void**)&rk,  g_rk);
    cudaGetSymbolAddress((void**)&rv,  g_rv);
    cudaGetSymbolAddress((void**)&rw,  g_rw);

    cudaFuncSetAttribute(gemm_tf32<0>,
        cudaFuncAttributeMaxDynamicSharedMemorySize, GEMM_SMEM);
    cudaFuncSetAttribute(gemm_tf32<1>,
        cudaFuncAttributeMaxDynamicSharedMemorySize, GEMM_SMEM);
    cudaFuncSetAttribute(gemm_tf32<2>,
        cudaFuncAttributeMaxDynamicSharedMemorySize, GEMM_SMEM);
    cudaFuncSetAttribute(attn_kernel,
        cudaFuncAttributeMaxDynamicSharedMemorySize, ATT_SMEM);

    const int DD = DMODEL * DMODEL;
    const int n4x = MTOT * DMODEL / 4;   // 1048576
    const int n4w = DD / 4;              // 65536

    // L1: round inputs (q,k,v); L2: round weights (wq,wk,wv,wo -> g_rw)
    round3_kernel<<<dim3(256, 3), 256>>>((const float4*)q, (const float4*)k,
                                         (const float4*)v, (float4*)rq,
                                         (float4*)rk, (float4*)rv, n4x);
    round4_kernel<<<dim3(128, 4), 256>>>((const float4*)wq, (const float4*)wk,
                                         (const float4*)wv, (const float4*)wo,
                                         (float4*)rw, n4w);

    dim3 gg(DMODEL / 128, MTOT / 128);   // (4, 64)
    // L3-L5: projections (scale 1/sqrt(Dk)=0.125 fused into Q)
    gemm_tf32<1><<<gg, 256, GEMM_SMEM>>>(rq, rw + 0 * DD, bq, qh, 0.125f);
    gemm_tf32<1><<<gg, 256, GEMM_SMEM>>>(rk, rw + 1 * DD, bk, kh, 1.0f);
    gemm_tf32<2><<<gg, 256, GEMM_SMEM>>>(rv, rw + 2 * DD, bv, vh, 1.0f);

    // L6: attention (profiled by ncu -s 5 -c 1)
    attn_kernel<<<dim3(SEQ / QROWS, BATCH * NHEAD), 256, ATT_SMEM>>>();

    // L7: output projection
    gemm_tf32<0><<<gg, 256, GEMM_SMEM>>>(att, rw + 3 * DD, bo,
                                         (float*)d_out, 1.0f);
}